// round 1
// baseline (speedup 1.0000x reference)
#include <cuda_runtime.h>

#define MAX_N   (1 << 17)   // 131072 points (matches problem)
#define NMODELS 8
#define H       128
#define TILE    128
#define THREADS 256
#define APAD    132         // padded row stride for activations in smem

// ---------------- scratch (device globals: no allocations allowed) ----------
__device__ int    g_counts[NMODELS];
__device__ int    g_base[NMODELS];
__device__ int    g_offset[NMODELS];
__device__ int    g_tilebase[NMODELS + 1];
__device__ int    g_total_tiles;
__device__ int    g_idx[MAX_N];
__device__ int    g_perm[MAX_N];
__device__ float4 g_xg[MAX_N];

// ---------------- model index, must match reference bit-for-bit -------------
__device__ __forceinline__ int model_index(float x0, float x1, float x2) {
    const float den = 2.0f + 1e-6f;
    float u0 = (x0 + 1.0f) / den;
    float u1 = (x1 + 1.0f) / den;
    float u2 = (x2 + 1.0f) / den;
    // cell = int(u[::-1] * grid); idx = c0 + 2*c1 + 4*c2 with grid (2,2,2)
    int c0 = (int)(u2 * 2.0f);
    int c1 = (int)(u1 * 2.0f);
    int c2 = (int)(u0 * 2.0f);
    return c0 + 2 * c1 + 4 * c2;
}

// ---------------- pass 0: zero counters -------------------------------------
__global__ void k_init() {
    if (threadIdx.x < NMODELS) g_counts[threadIdx.x] = 0;
}

// ---------------- pass 1: classify + histogram (block-aggregated) -----------
__global__ void k_classify(const float* __restrict__ x, int n) {
    __shared__ int sh[NMODELS];
    if (threadIdx.x < NMODELS) sh[threadIdx.x] = 0;
    __syncthreads();
    int i = blockIdx.x * blockDim.x + threadIdx.x;
    if (i < n) {
        float x0 = x[3 * i + 0], x1 = x[3 * i + 1], x2 = x[3 * i + 2];
        int m = model_index(x0, x1, x2);
        g_idx[i] = m;
        atomicAdd(&sh[m], 1);
    }
    __syncthreads();
    if (threadIdx.x < NMODELS && sh[threadIdx.x])
        atomicAdd(&g_counts[threadIdx.x], sh[threadIdx.x]);
}

// ---------------- pass 2: tiny scan over 8 bins ------------------------------
__global__ void k_scan() {
    if (threadIdx.x == 0) {
        int acc = 0, t = 0;
        for (int m = 0; m < NMODELS; m++) {
            g_base[m]     = acc;
            g_offset[m]   = acc;
            g_tilebase[m] = t;
            t   += (g_counts[m] + TILE - 1) / TILE;
            acc += g_counts[m];
        }
        g_tilebase[NMODELS] = t;
        g_total_tiles = t;
    }
}

// ---------------- pass 3: scatter points into per-model groups ---------------
__global__ void k_scatter(const float* __restrict__ x,
                          const float* __restrict__ mins,
                          const float* __restrict__ maxs, int n) {
    __shared__ int sh_cnt[NMODELS];
    __shared__ int sh_base[NMODELS];
    int tid = threadIdx.x;
    if (tid < NMODELS) sh_cnt[tid] = 0;
    __syncthreads();
    int i = blockIdx.x * blockDim.x + tid;
    int m = 0, rank = 0;
    if (i < n) {
        m = g_idx[i];
        rank = atomicAdd(&sh_cnt[m], 1);   // rank within block for this model
    }
    __syncthreads();
    if (tid < NMODELS)
        sh_base[tid] = sh_cnt[tid] ? atomicAdd(&g_offset[tid], sh_cnt[tid]) : 0;
    __syncthreads();
    if (i < n) {
        int pos = sh_base[m] + rank;
        g_perm[pos] = i;
        float xn[3];
        #pragma unroll
        for (int d = 0; d < 3; d++) {
            float mn = mins[3 * m + d];
            float mx = maxs[3 * m + d];
            xn[d] = -1.0f + 2.0f * (x[3 * i + d] - mn) / (mx - mn);
        }
        g_xg[pos] = make_float4(xn[0], xn[1], xn[2], 0.0f);
    }
}

// ---------------- fused-MLP GEMM core (fp32, 8x8 microtile) ------------------
// C[128][H] = relu(A[128][H] @ Wg[H][H] + bg[H]) ; A,C in smem (APAD stride)
__device__ __forceinline__ void gemm_relu(const float* __restrict__ A,
                                          const float* __restrict__ Wg,
                                          const float* __restrict__ bg,
                                          float* __restrict__ C,
                                          float* __restrict__ Ws,   // [8][128]
                                          int tid) {
    const int tx = tid & 15;   // 16 cols of threads -> 8 outs each
    const int ty = tid >> 4;   // 16 rows of threads -> 8 points each

    float acc[8][8];
    #pragma unroll
    for (int r = 0; r < 8; r++)
        #pragma unroll
        for (int c = 0; c < 8; c++) acc[r][c] = 0.0f;

    float bb[8];
    #pragma unroll
    for (int c = 0; c < 8; c++) bb[c] = bg[tx * 8 + c];  // L1-cached, broadcast

    const int wr = tid >> 5;           // 0..7  (row of W panel)
    const int wj = (tid & 31) << 2;    // 0..124 (col*4)

    for (int kk = 0; kk < H; kk += 8) {
        __syncthreads();   // prior Ws readers done / A fully written (first iter)
        *(float4*)(Ws + wr * 128 + wj) =
            *(const float4*)(Wg + (kk + wr) * H + wj);
        __syncthreads();

        #pragma unroll
        for (int half = 0; half < 2; half++) {
            float4 a4[8];
            #pragma unroll
            for (int r = 0; r < 8; r++)
                a4[r] = *(const float4*)(A + (ty * 8 + r) * APAD + kk + half * 4);
            #pragma unroll
            for (int k = 0; k < 4; k++) {
                float w[8];
                float4 w0 = *(const float4*)(Ws + (half * 4 + k) * 128 + tx * 8);
                float4 w1 = *(const float4*)(Ws + (half * 4 + k) * 128 + tx * 8 + 4);
                w[0] = w0.x; w[1] = w0.y; w[2] = w0.z; w[3] = w0.w;
                w[4] = w1.x; w[5] = w1.y; w[6] = w1.z; w[7] = w1.w;
                #pragma unroll
                for (int r = 0; r < 8; r++) {
                    float a = (k == 0) ? a4[r].x : (k == 1) ? a4[r].y
                             : (k == 2) ? a4[r].z : a4[r].w;
                    #pragma unroll
                    for (int c = 0; c < 8; c++) acc[r][c] = fmaf(a, w[c], acc[r][c]);
                }
            }
        }
    }

    // epilogue: bias + relu, vectorized store
    #pragma unroll
    for (int r = 0; r < 8; r++) {
        float4 v0, v1;
        v0.x = fmaxf(acc[r][0] + bb[0], 0.0f);
        v0.y = fmaxf(acc[r][1] + bb[1], 0.0f);
        v0.z = fmaxf(acc[r][2] + bb[2], 0.0f);
        v0.w = fmaxf(acc[r][3] + bb[3], 0.0f);
        v1.x = fmaxf(acc[r][4] + bb[4], 0.0f);
        v1.y = fmaxf(acc[r][5] + bb[5], 0.0f);
        v1.z = fmaxf(acc[r][6] + bb[6], 0.0f);
        v1.w = fmaxf(acc[r][7] + bb[7], 0.0f);
        float* cp = C + (ty * 8 + r) * APAD + tx * 8;
        *(float4*)cp       = v0;
        *(float4*)(cp + 4) = v1;
    }
}

// ---------------- pass 4: fused 4-layer MLP, one CTA per 128-pt tile ---------
__global__ void __launch_bounds__(THREADS, 1)
k_mlp(const float* __restrict__ W0, const float* __restrict__ b0,
      const float* __restrict__ W1, const float* __restrict__ b1,
      const float* __restrict__ W2, const float* __restrict__ b2,
      const float* __restrict__ W3, const float* __restrict__ b3,
      float* __restrict__ out) {
    int t = blockIdx.x;
    if (t >= g_total_tiles) return;

    // find (model, tile-within-model); 8 bins, linear scan
    int m = 0;
    while (m < NMODELS - 1 && t >= g_tilebase[m + 1]) m++;
    const int tile = t - g_tilebase[m];
    const int row0 = g_base[m] + tile * TILE;
    const int rows = min(TILE, g_base[m] + g_counts[m] - row0);
    const int tid  = threadIdx.x;

    extern __shared__ float smem[];
    float*  As = smem;                       // [128][APAD]
    float*  Bs = smem + TILE * APAD;         // [128][APAD]
    float*  Ws = smem + 2 * TILE * APAD;     // [8][128] weight panel / W0 / w3
    float4* Xs = (float4*)(Ws + 8 * 128);    // [128] inputs

    // load (normalized) inputs; zero-pad ragged tail
    for (int p = tid; p < TILE; p += THREADS)
        Xs[p] = (p < rows) ? g_xg[row0 + p] : make_float4(0.f, 0.f, 0.f, 0.f);
    // stage W0 (3x128) into Ws
    for (int j = tid; j < 3 * H; j += THREADS) Ws[j] = W0[m * 3 * H + j];
    __syncthreads();

    // ---- layer 0: [128,3] -> relu -> As[128,128]
    const float* b0g = b0 + m * H;
    for (int e = tid; e < TILE * H; e += THREADS) {
        int p = e >> 7, j = e & 127;
        float4 xv = Xs[p];
        float h = fmaf(xv.x, Ws[j],
                  fmaf(xv.y, Ws[128 + j],
                  fmaf(xv.z, Ws[256 + j], b0g[j])));
        As[p * APAD + j] = fmaxf(h, 0.0f);
    }

    // ---- layer 1: As -> Bs   (gemm_relu's internal pre-sync covers As writes)
    gemm_relu(As, W1 + m * H * H, b1 + m * H, Bs, Ws, tid);
    // ---- layer 2: Bs -> As
    gemm_relu(Bs, W2 + m * H * H, b2 + m * H, As, Ws, tid);

    // ---- layer 3: [128,128] @ [128,1] + b3
    __syncthreads();                       // Ws readers of layer2 done
    if (tid < H) Ws[tid] = W3[m * H + tid];
    __syncthreads();
    if (tid < rows) {
        const float* ap = As + tid * APAD;
        float acc = b3[m];
        #pragma unroll 8
        for (int k = 0; k < H; k++) acc = fmaf(ap[k], Ws[k], acc);
        out[g_perm[row0 + tid]] = acc;
    }
}

// ---------------- launch -----------------------------------------------------
extern "C" void kernel_launch(void* const* d_in, const int* in_sizes, int n_in,
                              void* d_out, int out_size) {
    const float* x    = (const float*)d_in[0];
    const float* W0   = (const float*)d_in[1];
    const float* b0   = (const float*)d_in[2];
    const float* W1   = (const float*)d_in[3];
    const float* b1   = (const float*)d_in[4];
    const float* W2   = (const float*)d_in[5];
    const float* b2   = (const float*)d_in[6];
    const float* W3   = (const float*)d_in[7];
    const float* b3   = (const float*)d_in[8];
    const float* mins = (const float*)d_in[9];
    const float* maxs = (const float*)d_in[10];
    float* out = (float*)d_out;

    const int n = in_sizes[0] / 3;

    const size_t smem_bytes =
        (size_t)(2 * TILE * APAD + 8 * 128) * sizeof(float) + TILE * sizeof(float4);
    cudaFuncSetAttribute(k_mlp, cudaFuncAttributeMaxDynamicSharedMemorySize,
                         (int)smem_bytes);

    int blocks = (n + 255) / 256;
    k_init<<<1, 32>>>();
    k_classify<<<blocks, 256>>>(x, n);
    k_scan<<<1, 32>>>();
    k_scatter<<<blocks, 256>>>(x, mins, maxs, n);

    const int max_tiles = n / TILE + NMODELS + 1;
    k_mlp<<<max_tiles, THREADS, smem_bytes>>>(W0, b0, W1, b1, W2, b2, W3, b3, out);
}

// round 3
// speedup vs baseline: 1.1098x; 1.1098x over previous
#include <cuda_runtime.h>

#define MAX_N   (1 << 17)   // 131072 points (matches problem)
#define NMODELS 8
#define H       128
#define TILE    128
#define THREADS 256
#define APAD    132         // padded row stride for activations in smem

// ---------------- scratch (device globals: no allocations allowed) ----------
__device__ int    g_counts[NMODELS];
__device__ int    g_base[NMODELS];
__device__ int    g_offset[NMODELS];
__device__ int    g_tilebase[NMODELS + 1];
__device__ int    g_total_tiles;
__device__ int    g_idx[MAX_N];
__device__ int    g_perm[MAX_N];
__device__ float4 g_xg[MAX_N];

// ---------------- packed fp32x2 helpers (Blackwell FFMA2 path) ---------------
__device__ __forceinline__ double pack_dup(float a) {
    double d;
    asm("mov.b64 %0, {%1, %1};" : "=d"(d) : "f"(a));
    return d;
}
__device__ __forceinline__ void ffma2(double& acc, double a, double b) {
    asm("fma.rn.f32x2 %0, %1, %2, %0;" : "+d"(acc) : "d"(a), "d"(b));
}
__device__ __forceinline__ void unpack2(double v, float& x, float& y) {
    asm("mov.b64 {%0, %1}, %2;" : "=f"(x), "=f"(y) : "d"(v));
}

// ---------------- model index, must match reference bit-for-bit -------------
__device__ __forceinline__ int model_index(float x0, float x1, float x2) {
    const float den = 2.0f + 1e-6f;
    float u0 = (x0 + 1.0f) / den;
    float u1 = (x1 + 1.0f) / den;
    float u2 = (x2 + 1.0f) / den;
    int c0 = (int)(u2 * 2.0f);
    int c1 = (int)(u1 * 2.0f);
    int c2 = (int)(u0 * 2.0f);
    return c0 + 2 * c1 + 4 * c2;
}

// ---------------- pass 0: zero counters -------------------------------------
__global__ void k_init() {
    if (threadIdx.x < NMODELS) g_counts[threadIdx.x] = 0;
}

// ---------------- pass 1: classify + histogram (block-aggregated) -----------
__global__ void k_classify(const float* __restrict__ x, int n) {
    __shared__ int sh[NMODELS];
    if (threadIdx.x < NMODELS) sh[threadIdx.x] = 0;
    __syncthreads();
    int i = blockIdx.x * blockDim.x + threadIdx.x;
    if (i < n) {
        float x0 = x[3 * i + 0], x1 = x[3 * i + 1], x2 = x[3 * i + 2];
        int m = model_index(x0, x1, x2);
        g_idx[i] = m;
        atomicAdd(&sh[m], 1);
    }
    __syncthreads();
    if (threadIdx.x < NMODELS && sh[threadIdx.x])
        atomicAdd(&g_counts[threadIdx.x], sh[threadIdx.x]);
}

// ---------------- pass 2: tiny scan over 8 bins ------------------------------
__global__ void k_scan() {
    if (threadIdx.x == 0) {
        int acc = 0, t = 0;
        for (int m = 0; m < NMODELS; m++) {
            g_base[m]     = acc;
            g_offset[m]   = acc;
            g_tilebase[m] = t;
            t   += (g_counts[m] + TILE - 1) / TILE;
            acc += g_counts[m];
        }
        g_tilebase[NMODELS] = t;
        g_total_tiles = t;
    }
}

// ---------------- pass 3: scatter points into per-model groups ---------------
__global__ void k_scatter(const float* __restrict__ x,
                          const float* __restrict__ mins,
                          const float* __restrict__ maxs, int n) {
    __shared__ int sh_cnt[NMODELS];
    __shared__ int sh_base[NMODELS];
    int tid = threadIdx.x;
    if (tid < NMODELS) sh_cnt[tid] = 0;
    __syncthreads();
    int i = blockIdx.x * blockDim.x + tid;
    int m = 0, rank = 0;
    if (i < n) {
        m = g_idx[i];
        rank = atomicAdd(&sh_cnt[m], 1);
    }
    __syncthreads();
    if (tid < NMODELS)
        sh_base[tid] = sh_cnt[tid] ? atomicAdd(&g_offset[tid], sh_cnt[tid]) : 0;
    __syncthreads();
    if (i < n) {
        int pos = sh_base[m] + rank;
        g_perm[pos] = i;
        float xn[3];
        #pragma unroll
        for (int d = 0; d < 3; d++) {
            float mn = mins[3 * m + d];
            float mx = maxs[3 * m + d];
            xn[d] = -1.0f + 2.0f * (x[3 * i + d] - mn) / (mx - mn);
        }
        g_xg[pos] = make_float4(xn[0], xn[1], xn[2], 0.0f);
    }
}

// ---------------- fused-MLP GEMM core (FFMA2, 8x8 microtile) -----------------
// C[128][H] = relu(A[128][H] @ Wg[H][H] + bg[H]) ; A,C in smem (APAD stride)
// Accumulators packed pairwise over output columns: double acc[8][4].
// W pairs read directly as double2 (LDS.128); broadcast 'a' dup'd via mov.b64.
__device__ __forceinline__ void gemm_relu(const float* __restrict__ A,
                                          const float* __restrict__ Wg,
                                          const float* __restrict__ bg,
                                          float* __restrict__ C,
                                          float* __restrict__ Ws,   // [8][128]
                                          int tid) {
    const int tx = tid & 15;   // 16 cols of threads -> 8 outs each
    const int ty = tid >> 4;   // 16 rows of threads -> 8 points each

    double acc[8][4];
    #pragma unroll
    for (int r = 0; r < 8; r++)
        #pragma unroll
        for (int c = 0; c < 4; c++) acc[r][c] = 0.0;   // bits = {0.f, 0.f}

    float bb[8];
    #pragma unroll
    for (int c = 0; c < 8; c++) bb[c] = bg[tx * 8 + c];

    const int wr = tid >> 5;           // 0..7  (row of W panel)
    const int wj = (tid & 31) << 2;    // 0..124 (col*4)

    // register prefetch of chunk 0 (hides L2 latency off the critical path)
    float4 wreg = *(const float4*)(Wg + wr * H + wj);

    for (int kk = 0; kk < H; kk += 8) {
        __syncthreads();   // prior Ws readers done / A fully written (first iter)
        *(float4*)(Ws + wr * 128 + wj) = wreg;
        __syncthreads();
        if (kk + 8 < H)    // prefetch next panel while computing this one
            wreg = *(const float4*)(Wg + (kk + 8 + wr) * H + wj);

        #pragma unroll
        for (int half = 0; half < 2; half++) {
            float4 a4[8];
            #pragma unroll
            for (int r = 0; r < 8; r++)
                a4[r] = *(const float4*)(A + (ty * 8 + r) * APAD + kk + half * 4);
            #pragma unroll
            for (int k = 0; k < 4; k++) {
                const double2 wlo = *(const double2*)(Ws + (half * 4 + k) * 128 + tx * 8);
                const double2 whi = *(const double2*)(Ws + (half * 4 + k) * 128 + tx * 8 + 4);
                #pragma unroll
                for (int r = 0; r < 8; r++) {
                    float a = (k == 0) ? a4[r].x : (k == 1) ? a4[r].y
                             : (k == 2) ? a4[r].z : a4[r].w;
                    double ad = pack_dup(a);
                    ffma2(acc[r][0], ad, wlo.x);
                    ffma2(acc[r][1], ad, wlo.y);
                    ffma2(acc[r][2], ad, whi.x);
                    ffma2(acc[r][3], ad, whi.y);
                }
            }
        }
    }

    // epilogue: unpack + bias + relu, vectorized store
    #pragma unroll
    for (int r = 0; r < 8; r++) {
        float v[8];
        #pragma unroll
        for (int c = 0; c < 4; c++) unpack2(acc[r][c], v[2 * c], v[2 * c + 1]);
        float4 v0, v1;
        v0.x = fmaxf(v[0] + bb[0], 0.0f);
        v0.y = fmaxf(v[1] + bb[1], 0.0f);
        v0.z = fmaxf(v[2] + bb[2], 0.0f);
        v0.w = fmaxf(v[3] + bb[3], 0.0f);
        v1.x = fmaxf(v[4] + bb[4], 0.0f);
        v1.y = fmaxf(v[5] + bb[5], 0.0f);
        v1.z = fmaxf(v[6] + bb[6], 0.0f);
        v1.w = fmaxf(v[7] + bb[7], 0.0f);
        float* cp = C + (ty * 8 + r) * APAD + tx * 8;
        *(float4*)cp       = v0;
        *(float4*)(cp + 4) = v1;
    }
}

// ---------------- pass 4: fused 4-layer MLP, one CTA per 128-pt tile ---------
__global__ void __launch_bounds__(THREADS, 1)
k_mlp(const float* __restrict__ W0, const float* __restrict__ b0,
      const float* __restrict__ W1, const float* __restrict__ b1,
      const float* __restrict__ W2, const float* __restrict__ b2,
      const float* __restrict__ W3, const float* __restrict__ b3,
      float* __restrict__ out) {
    int t = blockIdx.x;
    if (t >= g_total_tiles) return;

    int m = 0;
    while (m < NMODELS - 1 && t >= g_tilebase[m + 1]) m++;
    const int tile = t - g_tilebase[m];
    const int row0 = g_base[m] + tile * TILE;
    const int rows = min(TILE, g_base[m] + g_counts[m] - row0);
    const int tid  = threadIdx.x;

    extern __shared__ float smem[];
    float*  As = smem;                       // [128][APAD]
    float*  Bs = smem + TILE * APAD;         // [128][APAD]
    float*  Ws = smem + 2 * TILE * APAD;     // [8][128] weight panel / W0 / w3
    float4* Xs = (float4*)(Ws + 8 * 128);    // [128] inputs

    for (int p = tid; p < TILE; p += THREADS)
        Xs[p] = (p < rows) ? g_xg[row0 + p] : make_float4(0.f, 0.f, 0.f, 0.f);
    for (int j = tid; j < 3 * H; j += THREADS) Ws[j] = W0[m * 3 * H + j];
    __syncthreads();

    // ---- layer 0: [128,3] -> relu -> As[128,128]
    const float* b0g = b0 + m * H;
    for (int e = tid; e < TILE * H; e += THREADS) {
        int p = e >> 7, j = e & 127;
        float4 xv = Xs[p];
        float h = fmaf(xv.x, Ws[j],
                  fmaf(xv.y, Ws[128 + j],
                  fmaf(xv.z, Ws[256 + j], b0g[j])));
        As[p * APAD + j] = fmaxf(h, 0.0f);
    }

    // ---- layer 1: As -> Bs   (gemm_relu's internal pre-sync covers As writes)
    gemm_relu(As, W1 + m * H * H, b1 + m * H, Bs, Ws, tid);
    // ---- layer 2: Bs -> As
    gemm_relu(Bs, W2 + m * H * H, b2 + m * H, As, Ws, tid);

    // ---- layer 3: [128,128] @ [128,1] + b3
    __syncthreads();                       // Ws readers of layer2 done
    if (tid < H) Ws[tid] = W3[m * H + tid];
    __syncthreads();
    if (tid < rows) {
        const float* ap = As + tid * APAD;
        float acc = b3[m];
        #pragma unroll 8
        for (int k = 0; k < H; k++) acc = fmaf(ap[k], Ws[k], acc);
        out[g_perm[row0 + tid]] = acc;
    }
}

// ---------------- launch -----------------------------------------------------
extern "C" void kernel_launch(void* const* d_in, const int* in_sizes, int n_in,
                              void* d_out, int out_size) {
    const float* x    = (const float*)d_in[0];
    const float* W0   = (const float*)d_in[1];
    const float* b0   = (const float*)d_in[2];
    const float* W1   = (const float*)d_in[3];
    const float* b1   = (const float*)d_in[4];
    const float* W2   = (const float*)d_in[5];
    const float* b2   = (const float*)d_in[6];
    const float* W3   = (const float*)d_in[7];
    const float* b3   = (const float*)d_in[8];
    const float* mins = (const float*)d_in[9];
    const float* maxs = (const float*)d_in[10];
    float* out = (float*)d_out;

    const int n = in_sizes[0] / 3;

    const size_t smem_bytes =
        (size_t)(2 * TILE * APAD + 8 * 128) * sizeof(float) + TILE * sizeof(float4);
    cudaFuncSetAttribute(k_mlp, cudaFuncAttributeMaxDynamicSharedMemorySize,
                         (int)smem_bytes);

    int blocks = (n + 255) / 256;
    k_init<<<1, 32>>>();
    k_classify<<<blocks, 256>>>(x, n);
    k_scan<<<1, 32>>>();
    k_scatter<<<blocks, 256>>>(x, mins, maxs, n);

    const int max_tiles = n / TILE + NMODELS + 1;
    k_mlp<<<max_tiles, THREADS, smem_bytes>>>(W0, b0, W1, b1, W2, b2, W3, b3, out);
}

// round 6
// speedup vs baseline: 3.4310x; 3.0915x over previous
#include <cuda_runtime.h>
#include <cuda_bf16.h>
#include <cstdint>

#define MAX_N   (1 << 17)
#define NMODELS 8
#define H       128
#define TILE    128
#define NCTA    148
#define MLP_THREADS 256

// B row stride: 128 bf16 = 256B + 16B pad = 272B = 68 u32 (ldmatrix conflict-free)
#define BSTRIDE_U32 68
#define BUF_U32     (H * BSTRIDE_U32)      // 8704 u32 = 34816 B per image

// ---------------- scratch (device globals; no allocs allowed) ----------------
__device__ int    g_counts[NMODELS];
__device__ int    g_base[NMODELS];
__device__ int    g_offset[NMODELS];
__device__ int    g_tilebase[NMODELS + 1];
__device__ int    g_total_tiles;
__device__ int    g_idx[MAX_N];
__device__ int    g_perm[MAX_N];
__device__ float4 g_xg[MAX_N];
// transposed bf16 weight images B[n][k] ([layer*8+model][n][k-pairs])
__device__ __align__(16) uint32_t g_Bhi[16 * BUF_U32];
__device__ __align__(16) uint32_t g_Blo[16 * BUF_U32];
// packed layer0: per model, per col: (w0, w1, w2, b0)
__device__ __align__(16) float4   g_W0p[NMODELS * H];

// ---------------- helpers -----------------------------------------------------
__device__ __forceinline__ uint32_t smem_u32(const void* p) {
    uint32_t a;
    asm("{ .reg .u64 t; cvta.to.shared.u64 t, %1; cvt.u32.u64 %0, t; }"
        : "=r"(a) : "l"(p));
    return a;
}
__device__ __forceinline__ void mma16816(float* d, const uint32_t* a,
                                         uint32_t b0, uint32_t b1) {
    asm volatile(
        "mma.sync.aligned.m16n8k16.row.col.f32.bf16.bf16.f32 "
        "{%0,%1,%2,%3}, {%4,%5,%6,%7}, {%8,%9}, {%0,%1,%2,%3};"
        : "+f"(d[0]), "+f"(d[1]), "+f"(d[2]), "+f"(d[3])
        : "r"(a[0]), "r"(a[1]), "r"(a[2]), "r"(a[3]), "r"(b0), "r"(b1));
}
__device__ __forceinline__ void ldsm4(uint32_t* r, uint32_t addr) {
    asm volatile("ldmatrix.sync.aligned.m8n8.x4.shared.b16 {%0,%1,%2,%3}, [%4];"
                 : "=r"(r[0]), "=r"(r[1]), "=r"(r[2]), "=r"(r[3]) : "r"(addr));
}
// pack (v0 -> low half, v1 -> high half) as bf16x2; also return residuals
__device__ __forceinline__ uint32_t pack_hi_res(float v0, float v1,
                                                float& r0, float& r1) {
    __nv_bfloat162 h = {__float2bfloat16_rn(v0), __float2bfloat16_rn(v1)};
    r0 = v0 - __bfloat162float(h.x);
    r1 = v1 - __bfloat162float(h.y);
    uint32_t u;
    memcpy(&u, &h, 4);
    return u;
}
__device__ __forceinline__ uint32_t pack_bf16x2(float lo_val, float hi_val) {
    uint32_t r;   // %1 -> upper half, %2 -> lower half
    asm("cvt.rn.bf16x2.f32 %0, %1, %2;" : "=r"(r) : "f"(hi_val), "f"(lo_val));
    return r;
}

// ---------------- model index (bit-exact vs reference) ------------------------
__device__ __forceinline__ int model_index(float x0, float x1, float x2) {
    const float den = 2.0f + 1e-6f;
    int c0 = (int)((x2 + 1.0f) / den * 2.0f);
    int c1 = (int)((x1 + 1.0f) / den * 2.0f);
    int c2 = (int)((x0 + 1.0f) / den * 2.0f);
    return c0 + 2 * c1 + 4 * c2;
}

// ---------------- aux passes --------------------------------------------------
__global__ void k_init() {
    if (threadIdx.x < NMODELS) g_counts[threadIdx.x] = 0;
}

__global__ void k_classify(const float* __restrict__ x, int n) {
    __shared__ int sh[NMODELS];
    if (threadIdx.x < NMODELS) sh[threadIdx.x] = 0;
    __syncthreads();
    int i = blockIdx.x * blockDim.x + threadIdx.x;
    if (i < n) {
        int m = model_index(x[3 * i], x[3 * i + 1], x[3 * i + 2]);
        g_idx[i] = m;
        atomicAdd(&sh[m], 1);
    }
    __syncthreads();
    if (threadIdx.x < NMODELS && sh[threadIdx.x])
        atomicAdd(&g_counts[threadIdx.x], sh[threadIdx.x]);
}

__global__ void k_scan() {
    if (threadIdx.x == 0) {
        int acc = 0, t = 0;
        for (int m = 0; m < NMODELS; m++) {
            g_base[m] = acc;
            g_offset[m] = acc;
            g_tilebase[m] = t;
            t += (g_counts[m] + TILE - 1) / TILE;
            acc += g_counts[m];
        }
        g_tilebase[NMODELS] = t;
        g_total_tiles = t;
    }
}

__global__ void k_scatter(const float* __restrict__ x,
                          const float* __restrict__ mins,
                          const float* __restrict__ maxs, int n) {
    __shared__ int sh_cnt[NMODELS];
    __shared__ int sh_base[NMODELS];
    int tid = threadIdx.x;
    if (tid < NMODELS) sh_cnt[tid] = 0;
    __syncthreads();
    int i = blockIdx.x * blockDim.x + tid;
    int m = 0, rank = 0;
    if (i < n) {
        m = g_idx[i];
        rank = atomicAdd(&sh_cnt[m], 1);
    }
    __syncthreads();
    if (tid < NMODELS)
        sh_base[tid] = sh_cnt[tid] ? atomicAdd(&g_offset[tid], sh_cnt[tid]) : 0;
    __syncthreads();
    if (i < n) {
        int pos = sh_base[m] + rank;
        g_perm[pos] = i;
        float xn[3];
        #pragma unroll
        for (int d = 0; d < 3; d++) {
            float mn = mins[3 * m + d], mx = maxs[3 * m + d];
            xn[d] = -1.0f + 2.0f * (x[3 * i + d] - mn) / (mx - mn);
        }
        g_xg[pos] = make_float4(xn[0], xn[1], xn[2], 0.0f);
    }
}

// ---------------- weight prep: transpose + hi/lo split ------------------------
__global__ void k_prep(const float* __restrict__ W1, const float* __restrict__ W2) {
    int idx = blockIdx.x * blockDim.x + threadIdx.x;
    if (idx >= 16 * 8192) return;
    int lm = idx >> 13;
    int k2 = (idx >> 7) & 63;
    int n  = idx & 127;                    // coalesced over n
    int l = lm >> 3, m = lm & 7;
    const float* W = (l ? W2 : W1) + m * H * H;
    float v0 = W[(2 * k2) * H + n];        // B[n][k] = W[k][n]
    float v1 = W[(2 * k2 + 1) * H + n];
    float r0, r1;
    uint32_t hi = pack_hi_res(v0, v1, r0, r1);
    uint32_t lo = pack_bf16x2(r0, r1);
    int off = lm * BUF_U32 + n * BSTRIDE_U32 + k2;
    g_Bhi[off] = hi;
    g_Blo[off] = lo;
}

__global__ void k_prep0(const float* __restrict__ W0, const float* __restrict__ b0) {
    int t = blockIdx.x * blockDim.x + threadIdx.x;
    if (t >= NMODELS * H) return;
    int m = t >> 7, c = t & 127;
    g_W0p[t] = make_float4(W0[m * 384 + c], W0[m * 384 + 128 + c],
                           W0[m * 384 + 256 + c], b0[m * H + c]);
}

// ---------------- smem layout (bytes) -----------------------------------------
#define SB_B1HI 0
#define SB_B1LO (SB_B1HI + 34816)
#define SB_B2HI (SB_B1LO + 34816)
#define SB_B2LO (SB_B2HI + 34816)
#define SB_W0P  (SB_B2LO + 34816)          // 128 * float4 = 2048
#define SB_B1   (SB_W0P + 2048)            // 512
#define SB_B2   (SB_B1 + 512)
#define SB_W3   (SB_B2 + 512)
#define SMEM_TOTAL (SB_W3 + 512)

// one GEMM layer: acc[64] += split-bf16( A-frags ) @ B(smem images)
__device__ __forceinline__ void mma_layer(float* acc,
                                          const uint32_t* a_hi,
                                          const uint32_t* a_lo,
                                          uint32_t bhi_base, uint32_t blo_base,
                                          uint32_t lane_off) {
    #pragma unroll
    for (int kt = 0; kt < 8; kt++) {
        #pragma unroll
        for (int ntp = 0; ntp < 8; ntp++) {
            uint32_t bh[4], bl[4];
            uint32_t off = (uint32_t)(ntp * 16 * 272 + kt * 32) + lane_off;
            ldsm4(bh, bhi_base + off);
            ldsm4(bl, blo_base + off);
            float* d0 = acc + (2 * ntp) * 4;
            float* d1 = acc + (2 * ntp + 1) * 4;
            mma16816(d0, a_hi + kt * 4, bh[0], bh[1]);
            mma16816(d0, a_lo + kt * 4, bh[0], bh[1]);
            mma16816(d0, a_hi + kt * 4, bl[0], bl[1]);
            mma16816(d1, a_hi + kt * 4, bh[2], bh[3]);
            mma16816(d1, a_lo + kt * 4, bh[2], bh[3]);
            mma16816(d1, a_hi + kt * 4, bl[2], bl[3]);
        }
    }
}

// ---------------- persistent fused-MLP kernel ---------------------------------
__global__ void __launch_bounds__(MLP_THREADS, 1)
k_mlp(const float* __restrict__ W3, const float* __restrict__ b1g,
      const float* __restrict__ b2g, const float* __restrict__ b3g,
      float* __restrict__ out) {
    extern __shared__ char smc[];
    const uint32_t sbase = smem_u32(smc);
    const int tid  = threadIdx.x;
    const int wid  = tid >> 5;
    const int lane = tid & 31;
    const int q2   = 2 * (lane & 3);
    const int grp  = lane >> 2;            // 0..7
    const int r0l  = wid * 16 + grp;       // local row A
    const int r1l  = r0l + 8;              // local row B

    // ldmatrix per-lane base offset within a B image
    const uint32_t lane_off =
        (uint32_t)(((lane & 7) + ((lane & 16) ? 8 : 0)) * 272 + ((lane & 8) ? 16 : 0));

    const int T = g_total_tiles;
    const int start = (int)((long long)blockIdx.x * T / NCTA);
    const int end   = (int)((long long)(blockIdx.x + 1) * T / NCTA);

    float4* W0ps = (float4*)(smc + SB_W0P);
    float*  b1s  = (float*)(smc + SB_B1);
    float*  b2s  = (float*)(smc + SB_B2);
    float*  w3s  = (float*)(smc + SB_W3);

    int cur_m = -1;
    float b3v = 0.0f;

    for (int t = start; t < end; t++) {
        int m = 0;
        while (m < NMODELS - 1 && t >= g_tilebase[m + 1]) m++;

        if (m != cur_m) {
            __syncthreads();               // prior tile's ldmatrix readers done
            // copy the 4 weight images (2176 uint4 each)
            const uint4* s1h = (const uint4*)(g_Bhi + (0 * 8 + m) * BUF_U32);
            const uint4* s1l = (const uint4*)(g_Blo + (0 * 8 + m) * BUF_U32);
            const uint4* s2h = (const uint4*)(g_Bhi + (1 * 8 + m) * BUF_U32);
            const uint4* s2l = (const uint4*)(g_Blo + (1 * 8 + m) * BUF_U32);
            uint4* d1h = (uint4*)(smc + SB_B1HI);
            uint4* d1l = (uint4*)(smc + SB_B1LO);
            uint4* d2h = (uint4*)(smc + SB_B2HI);
            uint4* d2l = (uint4*)(smc + SB_B2LO);
            for (int i = tid; i < 2176; i += MLP_THREADS) {
                d1h[i] = s1h[i];
                d1l[i] = s1l[i];
                d2h[i] = s2h[i];
                d2l[i] = s2l[i];
            }
            if (tid < H) {
                W0ps[tid] = g_W0p[m * H + tid];
                b1s[tid]  = b1g[m * H + tid];
                b2s[tid]  = b2g[m * H + tid];
                w3s[tid]  = W3[m * H + tid];
            }
            b3v = b3g[m];
            cur_m = m;
            __syncthreads();
        }

        const int row0 = g_base[m] + (t - g_tilebase[m]) * TILE;
        const int rows = min(TILE, g_base[m] + g_counts[m] - row0);

        // ---- layer 0: compute A-fragments directly in registers -------------
        float4 xa = (r0l < rows) ? g_xg[row0 + r0l] : make_float4(0.f, 0.f, 0.f, 0.f);
        float4 xb = (r1l < rows) ? g_xg[row0 + r1l] : make_float4(0.f, 0.f, 0.f, 0.f);

        uint32_t a_hi[32], a_lo[32];
        #pragma unroll
        for (int kt = 0; kt < 8; kt++) {
            int c0 = kt * 16 + q2;
            float4 wA0 = W0ps[c0], wA1 = W0ps[c0 + 1];
            float4 wB0 = W0ps[c0 + 8], wB1 = W0ps[c0 + 9];
            float va0 = fmaxf(fmaf(xa.x, wA0.x, fmaf(xa.y, wA0.y, fmaf(xa.z, wA0.z, wA0.w))), 0.f);
            float va1 = fmaxf(fmaf(xa.x, wA1.x, fmaf(xa.y, wA1.y, fmaf(xa.z, wA1.z, wA1.w))), 0.f);
            float vb0 = fmaxf(fmaf(xb.x, wA0.x, fmaf(xb.y, wA0.y, fmaf(xb.z, wA0.z, wA0.w))), 0.f);
            float vb1 = fmaxf(fmaf(xb.x, wA1.x, fmaf(xb.y, wA1.y, fmaf(xb.z, wA1.z, wA1.w))), 0.f);
            float va2 = fmaxf(fmaf(xa.x, wB0.x, fmaf(xa.y, wB0.y, fmaf(xa.z, wB0.z, wB0.w))), 0.f);
            float va3 = fmaxf(fmaf(xa.x, wB1.x, fmaf(xa.y, wB1.y, fmaf(xa.z, wB1.z, wB1.w))), 0.f);
            float vb2 = fmaxf(fmaf(xb.x, wB0.x, fmaf(xb.y, wB0.y, fmaf(xb.z, wB0.z, wB0.w))), 0.f);
            float vb3 = fmaxf(fmaf(xb.x, wB1.x, fmaf(xb.y, wB1.y, fmaf(xb.z, wB1.z, wB1.w))), 0.f);
            float ra0, ra1, rb0, rb1, ra2, ra3, rb2, rb3;
            a_hi[kt * 4 + 0] = pack_hi_res(va0, va1, ra0, ra1);
            a_hi[kt * 4 + 1] = pack_hi_res(vb0, vb1, rb0, rb1);
            a_hi[kt * 4 + 2] = pack_hi_res(va2, va3, ra2, ra3);
            a_hi[kt * 4 + 3] = pack_hi_res(vb2, vb3, rb2, rb3);
            a_lo[kt * 4 + 0] = pack_bf16x2(ra0, ra1);
            a_lo[kt * 4 + 1] = pack_bf16x2(rb0, rb1);
            a_lo[kt * 4 + 2] = pack_bf16x2(ra2, ra3);
            a_lo[kt * 4 + 3] = pack_bf16x2(rb2, rb3);
        }

        // ---- layer 1 ---------------------------------------------------------
        float acc[64];
        #pragma unroll
        for (int i = 0; i < 64; i++) acc[i] = 0.0f;
        mma_layer(acc, a_hi, a_lo, sbase + SB_B1HI, sbase + SB_B1LO, lane_off);

        // epilogue: bias + relu -> new A-fragments (C frag layout == A frag layout)
        #pragma unroll
        for (int kt = 0; kt < 8; kt++) {
            int ntA = 2 * kt, ntB = 2 * kt + 1;
            int cbA = ntA * 8 + q2, cbB = ntB * 8 + q2;
            float bA0 = b1s[cbA], bA1 = b1s[cbA + 1];
            float bB0 = b1s[cbB], bB1 = b1s[cbB + 1];
            float va0 = fmaxf(acc[ntA * 4 + 0] + bA0, 0.f);
            float va1 = fmaxf(acc[ntA * 4 + 1] + bA1, 0.f);
            float vb0 = fmaxf(acc[ntA * 4 + 2] + bA0, 0.f);
            float vb1 = fmaxf(acc[ntA * 4 + 3] + bA1, 0.f);
            float va2 = fmaxf(acc[ntB * 4 + 0] + bB0, 0.f);
            float va3 = fmaxf(acc[ntB * 4 + 1] + bB1, 0.f);
            float vb2 = fmaxf(acc[ntB * 4 + 2] + bB0, 0.f);
            float vb3 = fmaxf(acc[ntB * 4 + 3] + bB1, 0.f);
            float ra0, ra1, rb0, rb1, ra2, ra3, rb2, rb3;
            a_hi[kt * 4 + 0] = pack_hi_res(va0, va1, ra0, ra1);
            a_hi[kt * 4 + 1] = pack_hi_res(vb0, vb1, rb0, rb1);
            a_hi[kt * 4 + 2] = pack_hi_res(va2, va3, ra2, ra3);
            a_hi[kt * 4 + 3] = pack_hi_res(vb2, vb3, rb2, rb3);
            a_lo[kt * 4 + 0] = pack_bf16x2(ra0, ra1);
            a_lo[kt * 4 + 1] = pack_bf16x2(rb0, rb1);
            a_lo[kt * 4 + 2] = pack_bf16x2(ra2, ra3);
            a_lo[kt * 4 + 3] = pack_bf16x2(rb2, rb3);
        }

        // ---- layer 2 ---------------------------------------------------------
        #pragma unroll
        for (int i = 0; i < 64; i++) acc[i] = 0.0f;
        mma_layer(acc, a_hi, a_lo, sbase + SB_B2HI, sbase + SB_B2LO, lane_off);

        // ---- layer 3: relu + dot(w3) + cross-lane reduce ---------------------
        float s0 = 0.f, s1 = 0.f;
        #pragma unroll
        for (int nt = 0; nt < 16; nt++) {
            int cb = nt * 8 + q2;
            float w3a = w3s[cb], w3b = w3s[cb + 1];
            float b2a = b2s[cb], b2b = b2s[cb + 1];
            s0 = fmaf(fmaxf(acc[nt * 4 + 0] + b2a, 0.f), w3a, s0);
            s0 = fmaf(fmaxf(acc[nt * 4 + 1] + b2b, 0.f), w3b, s0);
            s1 = fmaf(fmaxf(acc[nt * 4 + 2] + b2a, 0.f), w3a, s1);
            s1 = fmaf(fmaxf(acc[nt * 4 + 3] + b2b, 0.f), w3b, s1);
        }
        s0 += __shfl_xor_sync(0xffffffffu, s0, 1);
        s0 += __shfl_xor_sync(0xffffffffu, s0, 2);
        s1 += __shfl_xor_sync(0xffffffffu, s1, 1);
        s1 += __shfl_xor_sync(0xffffffffu, s1, 2);
        if ((lane & 3) == 0) {
            if (r0l < rows) out[g_perm[row0 + r0l]] = s0 + b3v;
            if (r1l < rows) out[g_perm[row0 + r1l]] = s1 + b3v;
        }
    }
}

// ---------------- launch -------------------------------------------------------
extern "C" void kernel_launch(void* const* d_in, const int* in_sizes, int n_in,
                              void* d_out, int out_size) {
    const float* x    = (const float*)d_in[0];
    const float* W0   = (const float*)d_in[1];
    const float* b0   = (const float*)d_in[2];
    const float* W1   = (const float*)d_in[3];
    const float* b1   = (const float*)d_in[4];
    const float* W2   = (const float*)d_in[5];
    const float* b2   = (const float*)d_in[6];
    const float* W3   = (const float*)d_in[7];
    const float* b3   = (const float*)d_in[8];
    const float* mins = (const float*)d_in[9];
    const float* maxs = (const float*)d_in[10];
    float* out = (float*)d_out;

    const int n = in_sizes[0] / 3;

    cudaFuncSetAttribute(k_mlp, cudaFuncAttributeMaxDynamicSharedMemorySize,
                         SMEM_TOTAL);

    int blocks = (n + 255) / 256;
    k_init<<<1, 32>>>();
    k_classify<<<blocks, 256>>>(x, n);
    k_scan<<<1, 32>>>();
    k_scatter<<<blocks, 256>>>(x, mins, maxs, n);
    k_prep<<<(16 * 8192 + 255) / 256, 256>>>(W1, W2);
    k_prep0<<<(NMODELS * H + 255) / 256, 256>>>(W0, b0);

    k_mlp<<<NCTA, MLP_THREADS, SMEM_TOTAL>>>(W3, b1, b2, b3, out);
}